// round 2
// baseline (speedup 1.0000x reference)
#include <cuda_runtime.h>
#include <cuda_bf16.h>

// Shapes fixed by the problem definition.
#define BATCH 256
#define HWPIX 1024            // 32*32
#define CHAN  256
#define NPART 4
#define PSIZE 64              // BATCH / NPART
#define EPSV  0.001f
#define NCHUNK 4              // pixel chunks per batch (256 pixels each)

// Scratch (allocation-free rule): device globals. All are fully overwritten
// every replay -> no zero-init kernel needed, graph-replay deterministic.
__device__ float g_psum[BATCH * NCHUNK][CHAN];   // per-(batch,chunk) partial sums
__device__ float g_psq [BATCH * NCHUNK][CHAN];   // per-(batch,chunk) partial sumsq
__device__ float g_scale[NPART][CHAN];
__device__ float g_bias [NPART][CHAN];
__device__ int   g_part[BATCH];

// ---------------------------------------------------------------------------
// Kernel 1: per-(batch,chunk,channel) partial sums. grid=(BATCH, NCHUNK),
// block=256. Thread: c4 = tid&63 (channel quad), psub = tid>>6 (pixel subgrp).
// Streams x FORWARD with default cache policy so x's chunk tails stay in L2
// for k_norm. Writes partials (no atomics, no init dependency).
// ---------------------------------------------------------------------------
__global__ void k_stats(const float4* __restrict__ x) {
    const int b     = blockIdx.x;
    const int chunk = blockIdx.y;
    const int t     = threadIdx.x;
    const int c4    = t & 63;
    const int psub  = t >> 6;

    const float4* base = x + ((size_t)b * HWPIX + (size_t)chunk * 256) * (CHAN / 4) + c4;

    float4 s = make_float4(0.f, 0.f, 0.f, 0.f);
    float4 q = make_float4(0.f, 0.f, 0.f, 0.f);
    #pragma unroll 8
    for (int i = 0; i < 64; i++) {
        float4 v = base[(size_t)(i * 4 + psub) * (CHAN / 4)];
        s.x += v.x; s.y += v.y; s.z += v.z; s.w += v.w;
        q.x += v.x * v.x; q.y += v.y * v.y; q.z += v.z * v.z; q.w += v.w * v.w;
    }

    __shared__ float ssum[4][CHAN];
    __shared__ float ssq[4][CHAN];
    const int cbase = c4 * 4;
    ssum[psub][cbase + 0] = s.x; ssum[psub][cbase + 1] = s.y;
    ssum[psub][cbase + 2] = s.z; ssum[psub][cbase + 3] = s.w;
    ssq[psub][cbase + 0]  = q.x; ssq[psub][cbase + 1]  = q.y;
    ssq[psub][cbase + 2]  = q.z; ssq[psub][cbase + 3]  = q.w;
    __syncthreads();

    const int pidx = b * NCHUNK + chunk;
    g_psum[pidx][t] = ssum[0][t] + ssum[1][t] + ssum[2][t] + ssum[3][t];
    g_psq[pidx][t]  = ssq[0][t]  + ssq[1][t]  + ssq[2][t]  + ssq[3][t];
}

// ---------------------------------------------------------------------------
// Kernel 2: reduce partials -> fused scale/bias, and build the partition map.
// grid=(NPART), block=(CHAN). Partition p owns batches perm[p*64 .. p*64+63].
// Reads 4 MB of L2-hot partials; ~2us.
// ---------------------------------------------------------------------------
__global__ void k_finalize(const float* __restrict__ gamma,
                           const float* __restrict__ beta,
                           const int* __restrict__ perm) {
    const int p = blockIdx.x;
    const int c = threadIdx.x;

    __shared__ int sbatch[PSIZE];
    if (c < PSIZE) {
        int b = perm[p * PSIZE + c];
        sbatch[c] = b;
        g_part[b] = p;        // partition map for k_norm
    }
    __syncthreads();

    float s = 0.f, q = 0.f;
    #pragma unroll 4
    for (int j = 0; j < PSIZE; j++) {
        const int pbase = sbatch[j] * NCHUNK;
        #pragma unroll
        for (int ch = 0; ch < NCHUNK; ch++) {
            s += g_psum[pbase + ch][c];
            q += g_psq[pbase + ch][c];
        }
    }

    const float invN = 1.0f / (float)(PSIZE * HWPIX);
    float mean = s * invN;
    float var  = q * invN - mean * mean;
    float sc   = gamma[p * CHAN + c] * rsqrtf(var + EPSV);
    g_scale[p][c] = sc;
    g_bias[p][c]  = beta[p * CHAN + c] - mean * sc;
}

// ---------------------------------------------------------------------------
// Kernel 3: normalize. Same (batch,chunk) decomposition as k_stats, but
// iterates pixels in REVERSE so the first reads hit the x-tails k_stats left
// in L2. __ldcs / __stcs: evict-first loads (don't re-allocate x), streaming
// stores (don't let output evict the L2-resident x we're about to read).
// ---------------------------------------------------------------------------
__global__ void k_norm(const float4* __restrict__ x, float4* __restrict__ out) {
    const int b     = blockIdx.x;
    const int chunk = blockIdx.y;
    const int t     = threadIdx.x;
    const int c4    = t & 63;
    const int psub  = t >> 6;
    const int p     = g_part[b];

    const float4 sc = ((const float4*)g_scale)[p * (CHAN / 4) + c4];
    const float4 bi = ((const float4*)g_bias)[p * (CHAN / 4) + c4];

    const size_t base = ((size_t)b * HWPIX + (size_t)chunk * 256) * (CHAN / 4) + c4;

    #pragma unroll 8
    for (int i = 63; i >= 0; i--) {
        size_t idx = base + (size_t)(i * 4 + psub) * (CHAN / 4);
        float4 v = __ldcs(&x[idx]);
        v.x = v.x * sc.x + bi.x;
        v.y = v.y * sc.y + bi.y;
        v.z = v.z * sc.z + bi.z;
        v.w = v.w * sc.w + bi.w;
        __stcs(&out[idx], v);
    }
}

// ---------------------------------------------------------------------------
extern "C" void kernel_launch(void* const* d_in, const int* in_sizes, int n_in,
                              void* d_out, int out_size) {
    const float* x     = (const float*)d_in[0];
    const float* gamma = (const float*)d_in[1];
    const float* beta  = (const float*)d_in[2];
    const int*   perm  = (const int*)d_in[3];

    k_stats<<<dim3(BATCH, NCHUNK), 256>>>((const float4*)x);
    k_finalize<<<NPART, CHAN>>>(gamma, beta, perm);
    k_norm<<<dim3(BATCH, NCHUNK), 256>>>((const float4*)x, (float4*)d_out);
}